// round 8
// baseline (speedup 1.0000x reference)
#include <cuda_runtime.h>

// ---------------------------------------------------------------------------
// edge_exists_predictor — linear net folded to scalar-per-node propagation.
// R7: degree atomics fused into fill (k_degdinv deleted, dinv/pa fused into
// t0 which now runs after fill); bucketed edge packed into ONE 32-bit word
// (src:17 bits | dstLocal:8 bits) halving aggregation read traffic;
// int4-vectorized edge reads in both agg passes. 5 launches.
// ---------------------------------------------------------------------------

#define NMAX 100000
#define NB   512            // buckets
#define CAP  8192           // edges per bucket capacity (mean 6250)
#define EPB  4096           // edges staged per fill block

__device__ int   g_is64;
__device__ int   g_deg[NMAX];
__device__ float g_dinv[NMAX];
__device__ float g_ta[NMAX];      // t0
__device__ float g_pa[NMAX];      // dinv * t0
__device__ float g_tb[NMAX];      // t1
__device__ float g_pb[NMAX];      // dinv * t1
__device__ float g_w1c[64];
__device__ float g_cst[3];        // c1, c2, cb
__device__ int   g_cur[NB];       // bucket fill cursors (= final counts)
__device__ unsigned g_bw[NB * CAP];  // packed (dstLocal<<17)|src

// --- init: zero deg + cursors; block 0: dtype detect + fold + out init ------
__global__ void k_init(const int* ei32,
                       const float* W1, const float* b1,
                       const float* W2, const float* b2,
                       const float* Wf1, const float* bf1,
                       const float* Wf2, const float* bf2,
                       const float* Wf3, const float* bf3,
                       const float* Wo,  const float* bo,
                       float* out, int G, int n) {
    int i = blockIdx.x * blockDim.x + threadIdx.x;
    if (i < n)  g_deg[i] = 0;
    if (i < NB) g_cur[i] = 0;

    if (blockIdx.x == 0) {
        __shared__ float v3[20], v2[30], v1[50], w2c[60];
        __shared__ float cb_s;
        int t = threadIdx.x;
        if (t == 0) {
            int z = ei32[1] | ei32[3] | ei32[5] | ei32[7] | ei32[9] | ei32[11];
            g_is64 = (z == 0) ? 1 : 0;
        }
        if (t < 20) { float s = 0.f; for (int j = 0; j < 10; j++) s += Wf3[t*10+j] * Wo[j]; v3[t] = s; }
        __syncthreads();
        if (t < 30) { float s = 0.f; for (int j = 0; j < 20; j++) s += Wf2[t*20+j] * v3[j]; v2[t] = s; }
        __syncthreads();
        if (t < 50) { float s = 0.f; for (int j = 0; j < 30; j++) s += Wf1[t*30+j] * v2[j]; v1[t] = s; }
        __syncthreads();
        if (t < 60) { float s = 0.f; for (int j = 0; j < 50; j++) s += W2[t*50+j] * v1[j]; w2c[t] = s; }
        __syncthreads();
        if (t < 64) { float s = 0.f; for (int j = 0; j < 60; j++) s += W1[t*60+j] * w2c[j]; g_w1c[t] = s; }
        if (t == 0) {
            float c1 = 0.f; for (int j = 0; j < 60; j++) c1 += b1[j] * w2c[j];
            float c2 = 0.f; for (int j = 0; j < 50; j++) c2 += b2[j] * v1[j];
            float cb = bo[0];
            for (int j = 0; j < 30; j++) cb += bf1[j] * v2[j];
            for (int j = 0; j < 20; j++) cb += bf2[j] * v3[j];
            for (int j = 0; j < 10; j++) cb += bf3[j] * Wo[j];
            g_cst[0] = c1; g_cst[1] = c2; g_cst[2] = cb; cb_s = cb;
        }
        __syncthreads();
        if (t < G) out[t] = cb_s;
    }
}

// --- fill: bucket edges by dst range; degree atomics fused ------------------
__global__ void k_fill(const void* ei, int E, unsigned magic, int range) {
    __shared__ int2 stage[EPB];     // 32 KB (src, dst)
    __shared__ int  hist[NB];       // 2 KB (then reused as local cursor)
    __shared__ int  basec[NB];      // 2 KB
    int tid   = threadIdx.x;
    int start = blockIdx.x * EPB;
    int cnt   = min(EPB, E - start);
    if (cnt <= 0) return;

    for (int b = tid; b < NB; b += 256) hist[b] = 0;
    __syncthreads();

    for (int k = tid; k < cnt; k += 256) {
        int idx = start + k;
        int s, d;
        if (g_is64) {
            const long long* p = (const long long*)ei;
            s = (int)p[idx]; d = (int)p[E + idx];
        } else {
            const int* p = (const int*)ei;
            s = p[idx]; d = p[E + idx];
        }
        stage[k] = make_int2(s, d);
        atomicAdd(&hist[__umulhi((unsigned)d, magic)], 1);
        atomicAdd(&g_deg[d], 1);
    }
    __syncthreads();

    for (int b = tid; b < NB; b += 256) {
        int h = hist[b];
        basec[b] = h ? atomicAdd(&g_cur[b], h) : 0;
        hist[b] = 0;                 // reuse as local cursor
    }
    __syncthreads();

    for (int k = tid; k < cnt; k += 256) {
        int2 e   = stage[k];
        int  b   = __umulhi((unsigned)e.y, magic);
        int dloc = e.y - b * range;
        int pos  = basec[b] + atomicAdd(&hist[b], 1);
        if (pos < CAP)
            g_bw[b * CAP + pos] = ((unsigned)dloc << 17) | (unsigned)e.x;
    }
}

// --- t0 = x . w1c (4 lanes/node) + dinv from deg + pa, fused ---------------
__global__ void k_t0(const float* __restrict__ x, int n) {
    int gt    = blockIdx.x * blockDim.x + threadIdx.x;
    int w     = gt >> 5;
    int lane  = threadIdx.x & 31;
    int node  = w * 8 + (lane >> 2);
    int sub   = lane & 3;
    bool live = (node < n);
    int nc    = live ? node : (n - 1);

    const float4* xp = (const float4*)x + nc * 16 + sub * 4;
    float4 a = xp[0], b = xp[1], c = xp[2], d = xp[3];
    const float4* wv = (const float4*)g_w1c + sub * 4;
    float4 wa = wv[0], wb = wv[1], wc = wv[2], wd = wv[3];

    float s0 = a.x*wa.x + a.y*wa.y + a.z*wa.z + a.w*wa.w;
    float s1 = b.x*wb.x + b.y*wb.y + b.z*wb.z + b.w*wb.w;
    float s2 = c.x*wc.x + c.y*wc.y + c.z*wc.z + c.w*wc.w;
    float s3 = d.x*wd.x + d.y*wd.y + d.z*wd.z + d.w*wd.w;
    float acc = (s0 + s1) + (s2 + s3);

    acc += __shfl_xor_sync(0xffffffffu, acc, 1);
    acc += __shfl_xor_sync(0xffffffffu, acc, 2);

    if (live && sub == 0) {
        float di = rsqrtf((float)(g_deg[node] + 1));
        g_dinv[node] = di;
        g_ta[node]   = acc;
        g_pa[node]   = di * acc;
    }
}

// --- layer 1: SMEM aggregation over packed bucket + finalize ---------------
__global__ void k_agg1(int n, int range) {
    __shared__ float acc[256];
    int b    = blockIdx.x;
    int tid  = threadIdx.x;
    int base = b * range;
    int nn   = min(range, n - base);
    if (nn <= 0) return;
    acc[tid] = 0.f;
    __syncthreads();
    int m  = min(g_cur[b], CAP);
    int m4 = m & ~3;
    const uint4* bw4 = (const uint4*)(g_bw + b * CAP);
    for (int i = tid * 4; i < m4; i += 1024) {
        uint4 w = bw4[i >> 2];
        atomicAdd(&acc[w.x >> 17], __ldg(&g_pa[w.x & 0x1FFFF]));
        atomicAdd(&acc[w.y >> 17], __ldg(&g_pa[w.y & 0x1FFFF]));
        atomicAdd(&acc[w.z >> 17], __ldg(&g_pa[w.z & 0x1FFFF]));
        atomicAdd(&acc[w.w >> 17], __ldg(&g_pa[w.w & 0x1FFFF]));
    }
    for (int i = m4 + tid; i < m; i += 256) {
        unsigned w = g_bw[b * CAP + i];
        atomicAdd(&acc[w >> 17], __ldg(&g_pa[w & 0x1FFFF]));
    }
    __syncthreads();
    if (tid < nn) {
        int node = base + tid;
        float di = g_dinv[node];
        float t1 = di * (acc[tid] + di * g_ta[node]) + g_cst[0];
        g_tb[node] = t1;
        g_pb[node] = di * t1;
    }
}

// --- layer 2: aggregation + finalize + pooled sum per graph -----------------
__global__ void k_agg2pool(const void* batch, float* out, int n, int range) {
    __shared__ float acc[256];
    int b    = blockIdx.x;
    int tid  = threadIdx.x;
    int lane = tid & 31;
    int base = b * range;
    int nn   = min(range, n - base);
    if (nn <= 0) return;
    acc[tid] = 0.f;
    __syncthreads();
    int m  = min(g_cur[b], CAP);
    int m4 = m & ~3;
    const uint4* bw4 = (const uint4*)(g_bw + b * CAP);
    for (int i = tid * 4; i < m4; i += 1024) {
        uint4 w = bw4[i >> 2];
        atomicAdd(&acc[w.x >> 17], __ldg(&g_pb[w.x & 0x1FFFF]));
        atomicAdd(&acc[w.y >> 17], __ldg(&g_pb[w.y & 0x1FFFF]));
        atomicAdd(&acc[w.z >> 17], __ldg(&g_pb[w.z & 0x1FFFF]));
        atomicAdd(&acc[w.w >> 17], __ldg(&g_pb[w.w & 0x1FFFF]));
    }
    for (int i = m4 + tid; i < m; i += 256) {
        unsigned w = g_bw[b * CAP + i];
        atomicAdd(&acc[w >> 17], __ldg(&g_pb[w & 0x1FFFF]));
    }
    __syncthreads();

    int node = min(base + tid, n - 1);
    int gid  = g_is64 ? (int)((const long long*)batch)[node]
                      : ((const int*)batch)[node];
    float v = 0.f;
    if (tid < nn) {
        float di = g_dinv[node];
        v = di * (acc[tid] + di * g_tb[node]) + g_cst[1];
    }
    int g0   = __shfl_sync(0xffffffffu, gid, 0);
    bool uni = __all_sync(0xffffffffu, gid == g0);
    if (uni) {
        #pragma unroll
        for (int o = 16; o; o >>= 1) v += __shfl_xor_sync(0xffffffffu, v, o);
        if (lane == 0) atomicAdd(&out[g0], v);
    } else {
        atomicAdd(&out[gid], v);
    }
}

extern "C" void kernel_launch(void* const* d_in, const int* in_sizes, int n_in,
                              void* d_out, int out_size) {
    const float* x     = (const float*)d_in[0];
    const void*  ei    = d_in[1];
    const void*  batch = d_in[2];
    const float* W1  = (const float*)d_in[3],  *b1  = (const float*)d_in[4];
    const float* W2  = (const float*)d_in[5],  *b2  = (const float*)d_in[6];
    const float* Wf1 = (const float*)d_in[7],  *bf1 = (const float*)d_in[8];
    const float* Wf2 = (const float*)d_in[9],  *bf2 = (const float*)d_in[10];
    const float* Wf3 = (const float*)d_in[11], *bf3 = (const float*)d_in[12];
    const float* Wo  = (const float*)d_in[13], *bo  = (const float*)d_in[14];
    float* out = (float*)d_out;

    int E = in_sizes[1] / 2;
    int n = in_sizes[2];
    int G = out_size;

    int range = (n + NB - 1) / NB;                              // 196
    unsigned magic = (unsigned)(((1ull << 32) + range - 1) / (unsigned)range);

    int nb = (n + 255) / 256;
    k_init<<<nb, 256>>>((const int*)ei, W1, b1, W2, b2,
                        Wf1, bf1, Wf2, bf2, Wf3, bf3, Wo, bo, out, G, n);
    k_fill<<<(E + EPB - 1) / EPB, 256>>>(ei, E, magic, range);
    k_t0<<<((n + 7) / 8 * 32 + 255) / 256, 256>>>(x, n);
    k_agg1<<<NB, 256>>>(n, range);
    k_agg2pool<<<NB, 256>>>(batch, out, n, range);
}

// round 9
// speedup vs baseline: 1.6199x; 1.6199x over previous
#include <cuda_runtime.h>

// ---------------------------------------------------------------------------
// edge_exists_predictor — linear net folded to scalar-per-node propagation.
// R8 = R6 structure (measured 86.5us) + ONE change: bucketed edges packed
// into a single 32-bit word (dstLocal<<17 | src), halving the bucket array
// (25.6 -> 12.8 MB) read by degdinv/agg1/agg2 and written by fill.
// Agg loops kept in R6's scalar 1-edge/iteration form (ptxas unrolls and
// front-batches the gathers; manual uint4+atomic interleave regressed 3x).
// ---------------------------------------------------------------------------

#define NMAX 100000
#define NB   512            // buckets
#define CAP  8192           // edges per bucket capacity (mean 6250)
#define EPB  4096           // edges staged per fill block

__device__ int   g_is64;
__device__ float g_dinv[NMAX];
__device__ float g_ta[NMAX];      // t0
__device__ float g_pa[NMAX];      // dinv * t0
__device__ float g_tb[NMAX];      // t1
__device__ float g_pb[NMAX];      // dinv * t1
__device__ float g_w1c[64];
__device__ float g_cst[3];        // c1, c2, cb
__device__ int   g_cur[NB];       // bucket fill cursors (= final counts)
__device__ unsigned g_bw[NB * CAP];  // packed (dstLocal<<17)|src

// --- init: zero cursors; block 0: dtype detect + weight fold + out init -----
__global__ void k_init(const int* ei32,
                       const float* W1, const float* b1,
                       const float* W2, const float* b2,
                       const float* Wf1, const float* bf1,
                       const float* Wf2, const float* bf2,
                       const float* Wf3, const float* bf3,
                       const float* Wo,  const float* bo,
                       float* out, int G) {
    int i = blockIdx.x * blockDim.x + threadIdx.x;
    if (i < NB) g_cur[i] = 0;

    if (blockIdx.x == 0) {
        __shared__ float v3[20], v2[30], v1[50], w2c[60];
        __shared__ float cb_s;
        int t = threadIdx.x;
        if (t == 0) {
            int z = ei32[1] | ei32[3] | ei32[5] | ei32[7] | ei32[9] | ei32[11];
            g_is64 = (z == 0) ? 1 : 0;
        }
        if (t < 20) { float s = 0.f; for (int j = 0; j < 10; j++) s += Wf3[t*10+j] * Wo[j]; v3[t] = s; }
        __syncthreads();
        if (t < 30) { float s = 0.f; for (int j = 0; j < 20; j++) s += Wf2[t*20+j] * v3[j]; v2[t] = s; }
        __syncthreads();
        if (t < 50) { float s = 0.f; for (int j = 0; j < 30; j++) s += Wf1[t*30+j] * v2[j]; v1[t] = s; }
        __syncthreads();
        if (t < 60) { float s = 0.f; for (int j = 0; j < 50; j++) s += W2[t*50+j] * v1[j]; w2c[t] = s; }
        __syncthreads();
        if (t < 64) { float s = 0.f; for (int j = 0; j < 60; j++) s += W1[t*60+j] * w2c[j]; g_w1c[t] = s; }
        if (t == 0) {
            float c1 = 0.f; for (int j = 0; j < 60; j++) c1 += b1[j] * w2c[j];
            float c2 = 0.f; for (int j = 0; j < 50; j++) c2 += b2[j] * v1[j];
            float cb = bo[0];
            for (int j = 0; j < 30; j++) cb += bf1[j] * v2[j];
            for (int j = 0; j < 20; j++) cb += bf2[j] * v3[j];
            for (int j = 0; j < 10; j++) cb += bf3[j] * Wo[j];
            g_cst[0] = c1; g_cst[1] = c2; g_cst[2] = cb; cb_s = cb;
        }
        __syncthreads();
        if (t < G) out[t] = cb_s;
    }
}

// --- t0 = x . w1c : 4 lanes/node, 8 nodes/warp ------------------------------
__global__ void k_t0(const float* __restrict__ x, int n) {
    int gt    = blockIdx.x * blockDim.x + threadIdx.x;
    int w     = gt >> 5;
    int lane  = threadIdx.x & 31;
    int node  = w * 8 + (lane >> 2);
    int sub   = lane & 3;
    bool live = (node < n);
    int nc    = live ? node : (n - 1);

    const float4* xp = (const float4*)x + nc * 16 + sub * 4;
    float4 a = xp[0], b = xp[1], c = xp[2], d = xp[3];
    const float4* wv = (const float4*)g_w1c + sub * 4;
    float4 wa = wv[0], wb = wv[1], wc = wv[2], wd = wv[3];

    float s0 = a.x*wa.x + a.y*wa.y + a.z*wa.z + a.w*wa.w;
    float s1 = b.x*wb.x + b.y*wb.y + b.z*wb.z + b.w*wb.w;
    float s2 = c.x*wc.x + c.y*wc.y + c.z*wc.z + c.w*wc.w;
    float s3 = d.x*wd.x + d.y*wd.y + d.z*wd.z + d.w*wd.w;
    float acc = (s0 + s1) + (s2 + s3);

    acc += __shfl_xor_sync(0xffffffffu, acc, 1);
    acc += __shfl_xor_sync(0xffffffffu, acc, 2);

    if (live && sub == 0) g_ta[node] = acc;
}

// --- fill: bucket edges by dst range, packed 32-bit writes ------------------
__global__ void k_fill(const void* ei, int E, unsigned magic, int range) {
    __shared__ int2 stage[EPB];     // 32 KB (src, dst)
    __shared__ int  hist[NB];       // 2 KB (then reused as local cursor)
    __shared__ int  basec[NB];      // 2 KB
    int tid   = threadIdx.x;
    int start = blockIdx.x * EPB;
    int cnt   = min(EPB, E - start);
    if (cnt <= 0) return;

    for (int b = tid; b < NB; b += 256) hist[b] = 0;
    __syncthreads();

    for (int k = tid; k < cnt; k += 256) {
        int idx = start + k;
        int s, d;
        if (g_is64) {
            const long long* p = (const long long*)ei;
            s = (int)p[idx]; d = (int)p[E + idx];
        } else {
            const int* p = (const int*)ei;
            s = p[idx]; d = p[E + idx];
        }
        stage[k] = make_int2(s, d);
        atomicAdd(&hist[__umulhi((unsigned)d, magic)], 1);
    }
    __syncthreads();

    for (int b = tid; b < NB; b += 256) {
        int h = hist[b];
        basec[b] = h ? atomicAdd(&g_cur[b], h) : 0;
        hist[b] = 0;                 // reuse as local cursor
    }
    __syncthreads();

    for (int k = tid; k < cnt; k += 256) {
        int2 e   = stage[k];
        int  b   = __umulhi((unsigned)e.y, magic);
        int dloc = e.y - b * range;
        int pos  = basec[b] + atomicAdd(&hist[b], 1);
        if (pos < CAP)
            g_bw[b * CAP + pos] = ((unsigned)dloc << 17) | (unsigned)e.x;
    }
}

// --- per-bucket degree count -> dinv + pa = dinv*ta (dense writes) ----------
__global__ void k_degdinv(int n, int range) {
    __shared__ int cnt[256];
    int b    = blockIdx.x;
    int tid  = threadIdx.x;
    int base = b * range;
    int nn   = min(range, n - base);
    if (nn <= 0) return;
    cnt[tid] = 0;
    __syncthreads();
    int m = min(g_cur[b], CAP);
    for (int i = tid; i < m; i += 256)
        atomicAdd(&cnt[g_bw[b * CAP + i] >> 17], 1);
    __syncthreads();
    if (tid < nn) {
        int node = base + tid;
        float di = rsqrtf((float)(cnt[tid] + 1));
        g_dinv[node] = di;
        g_pa[node]   = di * g_ta[node];
    }
}

// --- layer 1: SMEM-accumulated aggregation + finalize (t1, p1) --------------
__global__ void k_agg1(int n, int range) {
    __shared__ float acc[256];
    int b    = blockIdx.x;
    int tid  = threadIdx.x;
    int base = b * range;
    int nn   = min(range, n - base);
    if (nn <= 0) return;
    acc[tid] = 0.f;
    __syncthreads();
    int m = min(g_cur[b], CAP);
    for (int i = tid; i < m; i += 256) {
        unsigned w = g_bw[b * CAP + i];
        atomicAdd(&acc[w >> 17], __ldg(&g_pa[w & 0x1FFFF]));
    }
    __syncthreads();
    if (tid < nn) {
        int node = base + tid;
        float di = g_dinv[node];
        float t1 = di * (acc[tid] + di * g_ta[node]) + g_cst[0];
        g_tb[node] = t1;
        g_pb[node] = di * t1;
    }
}

// --- layer 2: aggregation + finalize + pooled sum per graph -----------------
__global__ void k_agg2pool(const void* batch, float* out, int n, int range) {
    __shared__ float acc[256];
    int b    = blockIdx.x;
    int tid  = threadIdx.x;
    int lane = tid & 31;
    int base = b * range;
    int nn   = min(range, n - base);
    if (nn <= 0) return;
    acc[tid] = 0.f;
    __syncthreads();
    int m = min(g_cur[b], CAP);
    for (int i = tid; i < m; i += 256) {
        unsigned w = g_bw[b * CAP + i];
        atomicAdd(&acc[w >> 17], __ldg(&g_pb[w & 0x1FFFF]));
    }
    __syncthreads();

    int node = min(base + tid, n - 1);
    int gid  = g_is64 ? (int)((const long long*)batch)[node]
                      : ((const int*)batch)[node];
    float v = 0.f;
    if (tid < nn) {
        float di = g_dinv[node];
        v = di * (acc[tid] + di * g_tb[node]) + g_cst[1];
    }
    int g0   = __shfl_sync(0xffffffffu, gid, 0);
    bool uni = __all_sync(0xffffffffu, gid == g0);
    if (uni) {
        #pragma unroll
        for (int o = 16; o; o >>= 1) v += __shfl_xor_sync(0xffffffffu, v, o);
        if (lane == 0) atomicAdd(&out[g0], v);
    } else {
        atomicAdd(&out[gid], v);
    }
}

extern "C" void kernel_launch(void* const* d_in, const int* in_sizes, int n_in,
                              void* d_out, int out_size) {
    const float* x     = (const float*)d_in[0];
    const void*  ei    = d_in[1];
    const void*  batch = d_in[2];
    const float* W1  = (const float*)d_in[3],  *b1  = (const float*)d_in[4];
    const float* W2  = (const float*)d_in[5],  *b2  = (const float*)d_in[6];
    const float* Wf1 = (const float*)d_in[7],  *bf1 = (const float*)d_in[8];
    const float* Wf2 = (const float*)d_in[9],  *bf2 = (const float*)d_in[10];
    const float* Wf3 = (const float*)d_in[11], *bf3 = (const float*)d_in[12];
    const float* Wo  = (const float*)d_in[13], *bo  = (const float*)d_in[14];
    float* out = (float*)d_out;

    int E = in_sizes[1] / 2;
    int n = in_sizes[2];
    int G = out_size;

    int range = (n + NB - 1) / NB;                              // 196
    unsigned magic = (unsigned)(((1ull << 32) + range - 1) / (unsigned)range);

    k_init<<<2, 256>>>((const int*)ei, W1, b1, W2, b2,
                       Wf1, bf1, Wf2, bf2, Wf3, bf3, Wo, bo, out, G);
    k_t0<<<((n + 7) / 8 * 32 + 255) / 256, 256>>>(x, n);
    k_fill<<<(E + EPB - 1) / EPB, 256>>>(ei, E, magic, range);
    k_degdinv<<<NB, 256>>>(n, range);
    k_agg1<<<NB, 256>>>(n, range);
    k_agg2pool<<<NB, 256>>>(batch, out, n, range);
}